// round 1
// baseline (speedup 1.0000x reference)
#include <cuda_runtime.h>
#include <math.h>
#include <stdint.h>

// Problem dims (fixed by setup_inputs)
#define L_DIM   1024
#define S_DIM   64
#define H_DIM   768
#define AH      384          // NUM_HEADS * HEAD_DIM
#define NH      6
#define HD      64
#define M_TOK   65536        // B*L*S
#define MAX_DIST 20.0f

// ---------------- scratch (device globals; no allocs allowed) ----------------
__device__ __align__(16) float g_q[M_TOK * AH];
__device__ __align__(16) float g_k[M_TOK * AH];
__device__ __align__(16) float g_v[M_TOK * AH];
__device__ __align__(16) float g_ctx[M_TOK * AH];
__device__ __align__(16) float g_bias[S_DIM * S_DIM];

// ---------------- helpers ----------------
__device__ __forceinline__ unsigned f2tf(float f) {
    unsigned u;
    asm("cvt.rna.tf32.f32 %0, %1;" : "=r"(u) : "f"(f));
    return u;
}

__device__ __forceinline__ void mma_tf32(float* c, const unsigned* a, const unsigned* b) {
    asm volatile(
        "mma.sync.aligned.m16n8k8.row.col.f32.tf32.tf32.f32 "
        "{%0,%1,%2,%3}, {%4,%5,%6,%7}, {%8,%9}, {%0,%1,%2,%3};"
        : "+f"(c[0]), "+f"(c[1]), "+f"(c[2]), "+f"(c[3])
        : "r"(a[0]), "r"(a[1]), "r"(a[2]), "r"(a[3]), "r"(b[0]), "r"(b[1]));
}

// ---------------- FIRE bias + attention mask ----------------
__global__ void bias_kernel(const float* __restrict__ phylo, const float* __restrict__ am,
                            const float* __restrict__ cPtr, const float* __restrict__ w1,
                            const float* __restrict__ w2) {
    float c = fmaxf(cPtr[0], 0.f);
    float denom = logf(c * MAX_DIST + 1.f);
    for (int idx = threadIdx.x; idx < S_DIM * S_DIM; idx += blockDim.x) {
        int k = idx & 63;
        float r = logf(c * phylo[idx] + 1.f) / denom;
        float b = 0.f;
#pragma unroll
        for (int f = 0; f < 32; ++f) {
            float t = r * w1[f];
            float h = t / (1.f + __expf(-t));   // silu
            b += h * w2[f];
        }
        g_bias[idx] = b + am[k];
    }
}

// ---------------- tf32 GEMM:  C[M,N] = A[M,K] @ W[N,K]^T (+bias)(+resid) ----------------
// BM=128, BN=64, BK=32, 256 threads (8 warps: 4 x 2), warp tile 32x32.
#define BM 128
#define BN 64
#define BK 32
#define PA 132
#define PB 68

template <int KD, bool RES>
__global__ void __launch_bounds__(256) gemm_tf32(
    const float* __restrict__ A, const float* __restrict__ W,
    const float* __restrict__ bias, float* __restrict__ out,
    const float* __restrict__ resid, int ldo)
{
    __shared__ unsigned As[BK][PA];
    __shared__ unsigned Bs[BK][PB];

    const int tid = threadIdx.x;
    const int m0 = blockIdx.x * BM;
    const int n0 = blockIdx.y * BN;

    const int kgrp = (tid & 7) * 4;   // k offset of this thread's float4 within BK
    const int arow = tid >> 3;        // 0..31

    const float* Aptr = A + (size_t)(m0 + arow) * KD + kgrp;
    const float* Wptr = W + (size_t)(n0 + arow) * KD + kgrp;

    const int warp = tid >> 5;
    const int lane = tid & 31;
    const int wm = (warp & 3) * 32;
    const int wn = (warp >> 2) * 32;
    const int lk = lane & 3;
    const int lm = lane >> 2;

    float acc[2][4][4];
#pragma unroll
    for (int a = 0; a < 2; ++a)
#pragma unroll
        for (int b = 0; b < 4; ++b)
#pragma unroll
            for (int c = 0; c < 4; ++c) acc[a][b][c] = 0.f;

    const int NK = KD / BK;
    float4 aReg[4], bReg[2];

    // prologue: load tile 0
#pragma unroll
    for (int i = 0; i < 4; ++i) aReg[i] = *(const float4*)(Aptr + (size_t)i * 32 * KD);
#pragma unroll
    for (int i = 0; i < 2; ++i) bReg[i] = *(const float4*)(Wptr + (size_t)i * 32 * KD);

#pragma unroll
    for (int i = 0; i < 4; ++i) {
        As[kgrp + 0][arow + i * 32] = f2tf(aReg[i].x);
        As[kgrp + 1][arow + i * 32] = f2tf(aReg[i].y);
        As[kgrp + 2][arow + i * 32] = f2tf(aReg[i].z);
        As[kgrp + 3][arow + i * 32] = f2tf(aReg[i].w);
    }
#pragma unroll
    for (int i = 0; i < 2; ++i) {
        Bs[kgrp + 0][arow + i * 32] = f2tf(bReg[i].x);
        Bs[kgrp + 1][arow + i * 32] = f2tf(bReg[i].y);
        Bs[kgrp + 2][arow + i * 32] = f2tf(bReg[i].z);
        Bs[kgrp + 3][arow + i * 32] = f2tf(bReg[i].w);
    }
    __syncthreads();

    for (int kt = 0; kt < NK; ++kt) {
        if (kt + 1 < NK) {
            const float* Ap = Aptr + (size_t)(kt + 1) * BK;
            const float* Wp = Wptr + (size_t)(kt + 1) * BK;
#pragma unroll
            for (int i = 0; i < 4; ++i) aReg[i] = *(const float4*)(Ap + (size_t)i * 32 * KD);
#pragma unroll
            for (int i = 0; i < 2; ++i) bReg[i] = *(const float4*)(Wp + (size_t)i * 32 * KD);
        }

#pragma unroll
        for (int k8 = 0; k8 < 4; ++k8) {
            const int kb = k8 * 8;
            unsigned afr[2][4], bfr[4][2];
#pragma unroll
            for (int mt = 0; mt < 2; ++mt) {
                const int mb = wm + mt * 16;
                afr[mt][0] = As[kb + lk][mb + lm];
                afr[mt][1] = As[kb + lk][mb + lm + 8];
                afr[mt][2] = As[kb + lk + 4][mb + lm];
                afr[mt][3] = As[kb + lk + 4][mb + lm + 8];
            }
#pragma unroll
            for (int nt = 0; nt < 4; ++nt) {
                const int nb = wn + nt * 8 + lm;
                bfr[nt][0] = Bs[kb + lk][nb];
                bfr[nt][1] = Bs[kb + lk + 4][nb];
            }
#pragma unroll
            for (int mt = 0; mt < 2; ++mt)
#pragma unroll
                for (int nt = 0; nt < 4; ++nt)
                    mma_tf32(acc[mt][nt], afr[mt], bfr[nt]);
        }
        __syncthreads();
        if (kt + 1 < NK) {
#pragma unroll
            for (int i = 0; i < 4; ++i) {
                As[kgrp + 0][arow + i * 32] = f2tf(aReg[i].x);
                As[kgrp + 1][arow + i * 32] = f2tf(aReg[i].y);
                As[kgrp + 2][arow + i * 32] = f2tf(aReg[i].z);
                As[kgrp + 3][arow + i * 32] = f2tf(aReg[i].w);
            }
#pragma unroll
            for (int i = 0; i < 2; ++i) {
                Bs[kgrp + 0][arow + i * 32] = f2tf(bReg[i].x);
                Bs[kgrp + 1][arow + i * 32] = f2tf(bReg[i].y);
                Bs[kgrp + 2][arow + i * 32] = f2tf(bReg[i].z);
                Bs[kgrp + 3][arow + i * 32] = f2tf(bReg[i].w);
            }
            __syncthreads();
        }
    }

    // epilogue: c0,c1 @ (row=lm, col=2*lk..+1); c2,c3 @ (row=lm+8)
#pragma unroll
    for (int mt = 0; mt < 2; ++mt) {
#pragma unroll
        for (int nt = 0; nt < 4; ++nt) {
            const int col = n0 + wn + nt * 8 + 2 * lk;
            const float b0 = bias[col];
            const float b1 = bias[col + 1];
#pragma unroll
            for (int half = 0; half < 2; ++half) {
                const int row = m0 + wm + mt * 16 + lm + half * 8;
                float2 val;
                val.x = acc[mt][nt][half * 2 + 0] + b0;
                val.y = acc[mt][nt][half * 2 + 1] + b1;
                if (RES) {
                    const float* rp = resid + (size_t)row * ldo + col;
                    val.x += rp[0];
                    val.y += rp[1];
                }
                *(float2*)(out + (size_t)row * ldo + col) = val;
            }
        }
    }
}

// ---------------- fused attention core: per (l, h) ----------------
// scores = q@k^T * 1/8 + bias -> softmax -> ctx = p@v
__global__ void __launch_bounds__(256) attn_kernel() {
    const int l = blockIdx.x;
    const int h = blockIdx.y;
    const int tid = threadIdx.x;

    __shared__ float bufA[64][68];   // q, later p    [row][col]
    __shared__ float bufB[64][68];   // k^T (d-major), later v [row][col]

    const size_t base = (size_t)l * 64 * AH + (size_t)h * HD;
    const int sg = tid >> 4;    // 0..15
    const int dg = tid & 15;    // 0..15

    // load q and k^T
#pragma unroll
    for (int it = 0; it < 4; ++it) {
        const int s = sg + it * 16;
        float4 qv = *(const float4*)(g_q + base + (size_t)s * AH + dg * 4);
        *(float4*)&bufA[s][dg * 4] = qv;
        float4 kv = *(const float4*)(g_k + base + (size_t)s * AH + dg * 4);
        bufB[dg * 4 + 0][s] = kv.x;
        bufB[dg * 4 + 1][s] = kv.y;
        bufB[dg * 4 + 2][s] = kv.z;
        bufB[dg * 4 + 3][s] = kv.w;
    }
    __syncthreads();

    const int r0 = sg * 4;
    const int c0 = dg * 4;

    float acc[4][4] = {};
#pragma unroll 8
    for (int kk = 0; kk < 64; ++kk) {
        float4 kv = *(const float4*)&bufB[kk][c0];
        float q0 = bufA[r0 + 0][kk];
        float q1 = bufA[r0 + 1][kk];
        float q2 = bufA[r0 + 2][kk];
        float q3 = bufA[r0 + 3][kk];
        acc[0][0] += q0 * kv.x; acc[0][1] += q0 * kv.y; acc[0][2] += q0 * kv.z; acc[0][3] += q0 * kv.w;
        acc[1][0] += q1 * kv.x; acc[1][1] += q1 * kv.y; acc[1][2] += q1 * kv.z; acc[1][3] += q1 * kv.w;
        acc[2][0] += q2 * kv.x; acc[2][1] += q2 * kv.y; acc[2][2] += q2 * kv.z; acc[2][3] += q2 * kv.w;
        acc[3][0] += q3 * kv.x; acc[3][1] += q3 * kv.y; acc[3][2] += q3 * kv.z; acc[3][3] += q3 * kv.w;
    }
#pragma unroll
    for (int i = 0; i < 4; ++i)
#pragma unroll
        for (int j = 0; j < 4; ++j)
            acc[i][j] = acc[i][j] * 0.125f + g_bias[(r0 + i) * 64 + c0 + j];
    __syncthreads();   // all reads of bufA/bufB (q, k) complete

    // softmax per row; row r0+i spread over the 16-lane group (cg = dg)
#pragma unroll
    for (int i = 0; i < 4; ++i) {
        float m = fmaxf(fmaxf(acc[i][0], acc[i][1]), fmaxf(acc[i][2], acc[i][3]));
#pragma unroll
        for (int o = 8; o; o >>= 1) m = fmaxf(m, __shfl_xor_sync(0xffffffffu, m, o));
        float s = 0.f;
#pragma unroll
        for (int j = 0; j < 4; ++j) { acc[i][j] = __expf(acc[i][j] - m); s += acc[i][j]; }
#pragma unroll
        for (int o = 8; o; o >>= 1) s += __shfl_xor_sync(0xffffffffu, s, o);
        const float inv = 1.f / s;
#pragma unroll
        for (int j = 0; j < 4; ++j) acc[i][j] *= inv;
        float4 p4; p4.x = acc[i][0]; p4.y = acc[i][1]; p4.z = acc[i][2]; p4.w = acc[i][3];
        *(float4*)&bufA[r0 + i][c0] = p4;   // p overwrites q
    }

    // load v (overwrites k^T)
#pragma unroll
    for (int it = 0; it < 4; ++it) {
        const int s = sg + it * 16;
        float4 vv = *(const float4*)(g_v + base + (size_t)s * AH + dg * 4);
        *(float4*)&bufB[s][dg * 4] = vv;
    }
    __syncthreads();

    float o[4][4] = {};
#pragma unroll 8
    for (int cc = 0; cc < 64; ++cc) {
        float4 vv = *(const float4*)&bufB[cc][c0];
        float p0 = bufA[r0 + 0][cc];
        float p1 = bufA[r0 + 1][cc];
        float p2 = bufA[r0 + 2][cc];
        float p3 = bufA[r0 + 3][cc];
        o[0][0] += p0 * vv.x; o[0][1] += p0 * vv.y; o[0][2] += p0 * vv.z; o[0][3] += p0 * vv.w;
        o[1][0] += p1 * vv.x; o[1][1] += p1 * vv.y; o[1][2] += p1 * vv.z; o[1][3] += p1 * vv.w;
        o[2][0] += p2 * vv.x; o[2][1] += p2 * vv.y; o[2][2] += p2 * vv.z; o[2][3] += p2 * vv.w;
        o[3][0] += p3 * vv.x; o[3][1] += p3 * vv.y; o[3][2] += p3 * vv.z; o[3][3] += p3 * vv.w;
    }
#pragma unroll
    for (int i = 0; i < 4; ++i) {
        float4 ov; ov.x = o[i][0]; ov.y = o[i][1]; ov.z = o[i][2]; ov.w = o[i][3];
        *(float4*)(g_ctx + base + (size_t)(r0 + i) * AH + c0) = ov;
    }
}

// ---------------- LayerNorm (in place on d_out rows of 768) ----------------
__global__ void __launch_bounds__(256) ln_kernel(float* __restrict__ x,
                                                 const float* __restrict__ g,
                                                 const float* __restrict__ b) {
    const size_t row = blockIdx.x;
    float* p = x + row * H_DIM;
    const int tid = threadIdx.x;

    float v0 = p[tid], v1 = p[tid + 256], v2 = p[tid + 512];
    float s = v0 + v1 + v2;
    float q = v0 * v0 + v1 * v1 + v2 * v2;
#pragma unroll
    for (int o = 16; o; o >>= 1) {
        s += __shfl_xor_sync(0xffffffffu, s, o);
        q += __shfl_xor_sync(0xffffffffu, q, o);
    }
    __shared__ float ss[8], qs[8];
    __shared__ float mu_s, rs_s;
    if ((tid & 31) == 0) { ss[tid >> 5] = s; qs[tid >> 5] = q; }
    __syncthreads();
    if (tid == 0) {
        float S = 0.f, Q = 0.f;
#pragma unroll
        for (int i = 0; i < 8; ++i) { S += ss[i]; Q += qs[i]; }
        const float mu = S * (1.f / 768.f);
        const float var = Q * (1.f / 768.f) - mu * mu;
        mu_s = mu;
        rs_s = rsqrtf(var + 1e-12f);
    }
    __syncthreads();
    const float mu = mu_s, rs = rs_s;
    p[tid]       = (v0 - mu) * rs * g[tid]       + b[tid];
    p[tid + 256] = (v1 - mu) * rs * g[tid + 256] + b[tid + 256];
    p[tid + 512] = (v2 - mu) * rs * g[tid + 512] + b[tid + 512];
}

// ---------------- launch ----------------
extern "C" void kernel_launch(void* const* d_in, const int* in_sizes, int n_in,
                              void* d_out, int out_size) {
    const float* hidden = (const float*)d_in[0];
    const float* source = (const float*)d_in[1];
    const float* amask  = (const float*)d_in[2];
    const float* phylo  = (const float*)d_in[3];
    const float* cP     = (const float*)d_in[4];
    const float* w1     = (const float*)d_in[5];
    const float* w2     = (const float*)d_in[6];
    const float* Wq     = (const float*)d_in[7];
    const float* bq     = (const float*)d_in[8];
    const float* Wk     = (const float*)d_in[9];
    const float* bk     = (const float*)d_in[10];
    const float* Wv     = (const float*)d_in[11];
    const float* bv     = (const float*)d_in[12];
    const float* Wo     = (const float*)d_in[13];
    const float* bo     = (const float*)d_in[14];
    const float* lng    = (const float*)d_in[15];
    const float* lnb    = (const float*)d_in[16];
    float* out = (float*)d_out;

    void *qa, *ka, *va, *ca;
    cudaGetSymbolAddress(&qa, g_q);
    cudaGetSymbolAddress(&ka, g_k);
    cudaGetSymbolAddress(&va, g_v);
    cudaGetSymbolAddress(&ca, g_ctx);

    bias_kernel<<<1, 256>>>(phylo, amask, cP, w1, w2);

    dim3 gQKV(M_TOK / BM, AH / BN);
    gemm_tf32<H_DIM, false><<<gQKV, 256>>>(hidden, Wq, bq, (float*)qa, nullptr, AH);
    gemm_tf32<H_DIM, false><<<gQKV, 256>>>(source, Wk, bk, (float*)ka, nullptr, AH);
    gemm_tf32<H_DIM, false><<<gQKV, 256>>>(source, Wv, bv, (float*)va, nullptr, AH);

    attn_kernel<<<dim3(L_DIM, NH), 256>>>();

    dim3 gO(M_TOK / BM, H_DIM / BN);
    gemm_tf32<AH, true><<<gO, 256>>>((const float*)ca, Wo, bo, out, hidden, H_DIM);

    ln_kernel<<<M_TOK, 256>>>(out, lng, lnb);
}

// round 3
// speedup vs baseline: 1.6926x; 1.6926x over previous
#include <cuda_runtime.h>
#include <cuda_bf16.h>
#include <math.h>
#include <stdint.h>

#define L_DIM   1024
#define S_DIM   64
#define H_DIM   768
#define AH      384
#define NH      6
#define HD      64
#define M_TOK   65536
#define MAX_DIST 20.0f
#define ROWB    80          // padded smem row bytes (32 bf16 = 64B + 16B pad) -> conflict-free ldmatrix

// ---------------- scratch (device globals; no allocs allowed) ----------------
__device__ __align__(16) __nv_bfloat16 g_hidb[M_TOK * H_DIM];
__device__ __align__(16) __nv_bfloat16 g_srcb[M_TOK * H_DIM];
__device__ __align__(16) __nv_bfloat16 g_ctxb[M_TOK * AH];
__device__ __align__(16) float g_q[M_TOK * AH];
__device__ __align__(16) float g_k[M_TOK * AH];
__device__ __align__(16) float g_v[M_TOK * AH];
__device__ __align__(16) __nv_bfloat16 g_Wqb[AH * H_DIM];
__device__ __align__(16) __nv_bfloat16 g_Wkb[AH * H_DIM];
__device__ __align__(16) __nv_bfloat16 g_Wvb[AH * H_DIM];
__device__ __align__(16) __nv_bfloat16 g_Wob[H_DIM * AH];
__device__ __align__(16) float g_bias[S_DIM * S_DIM];

// ---------------- asm helpers ----------------
#define CPA(dst, src) asm volatile("cp.async.cg.shared.global [%0], [%1], 16;" :: "r"(dst), "l"(src))
#define CP_COMMIT()   asm volatile("cp.async.commit_group;")
#define CP_WAIT(n)    asm volatile("cp.async.wait_group %0;" :: "n"(n))

__device__ __forceinline__ void ldm_x4(unsigned& r0, unsigned& r1, unsigned& r2, unsigned& r3,
                                       unsigned addr) {
    asm volatile("ldmatrix.sync.aligned.m8n8.x4.shared.b16 {%0,%1,%2,%3}, [%4];"
                 : "=r"(r0), "=r"(r1), "=r"(r2), "=r"(r3) : "r"(addr));
}

__device__ __forceinline__ void mma_bf16(float* c, const unsigned* a, const unsigned* b) {
    asm volatile(
        "mma.sync.aligned.m16n8k16.row.col.f32.bf16.bf16.f32 "
        "{%0,%1,%2,%3},{%4,%5,%6,%7},{%8,%9},{%0,%1,%2,%3};"
        : "+f"(c[0]), "+f"(c[1]), "+f"(c[2]), "+f"(c[3])
        : "r"(a[0]), "r"(a[1]), "r"(a[2]), "r"(a[3]), "r"(b[0]), "r"(b[1]));
}

__device__ __forceinline__ unsigned pack_bf(float a, float b) {
    __nv_bfloat162 t = __floats2bfloat162_rn(a, b);   // a -> low, b -> high
    return *reinterpret_cast<unsigned*>(&t);
}

// ---------------- fp32 -> bf16 conversion passes ----------------
__global__ void __launch_bounds__(256) cvt_act(const float4* __restrict__ hid,
                                               const float4* __restrict__ src) {
    const int n = M_TOK * H_DIM / 4;
    uint2* oh = reinterpret_cast<uint2*>(g_hidb);
    uint2* os = reinterpret_cast<uint2*>(g_srcb);
    for (int i = blockIdx.x * blockDim.x + threadIdx.x; i < n; i += gridDim.x * blockDim.x) {
        float4 h = hid[i];
        oh[i] = make_uint2(pack_bf(h.x, h.y), pack_bf(h.z, h.w));
        float4 s = src[i];
        os[i] = make_uint2(pack_bf(s.x, s.y), pack_bf(s.z, s.w));
    }
}

__global__ void __launch_bounds__(256) cvt_w(const float4* __restrict__ wq,
                                             const float4* __restrict__ wk,
                                             const float4* __restrict__ wv,
                                             const float4* __restrict__ wo) {
    const int per = AH * H_DIM / 4;   // 73728 float4 per weight
    const int a = blockIdx.y;
    const float4* src = (a == 0) ? wq : (a == 1) ? wk : (a == 2) ? wv : wo;
    uint2* dst = (a == 0) ? (uint2*)g_Wqb : (a == 1) ? (uint2*)g_Wkb
               : (a == 2) ? (uint2*)g_Wvb : (uint2*)g_Wob;
    for (int i = blockIdx.x * blockDim.x + threadIdx.x; i < per; i += gridDim.x * blockDim.x) {
        float4 v = src[i];
        dst[i] = make_uint2(pack_bf(v.x, v.y), pack_bf(v.z, v.w));
    }
}

// ---------------- FIRE bias + attention mask ----------------
__global__ void bias_kernel(const float* __restrict__ phylo, const float* __restrict__ am,
                            const float* __restrict__ cPtr, const float* __restrict__ w1,
                            const float* __restrict__ w2) {
    float c = fmaxf(cPtr[0], 0.f);
    float denom = logf(c * MAX_DIST + 1.f);
    for (int idx = threadIdx.x; idx < S_DIM * S_DIM; idx += blockDim.x) {
        int k = idx & 63;
        float r = logf(c * phylo[idx] + 1.f) / denom;
        float b = 0.f;
#pragma unroll
        for (int f = 0; f < 32; ++f) {
            float t = r * w1[f];
            float h = t / (1.f + __expf(-t));
            b += h * w2[f];
        }
        g_bias[idx] = b + am[k];
    }
}

// ---------------- bf16 tensor-core GEMM: C[M,N] = A[M,K] @ W[N,K]^T (+bias)(+resid) ----------------
// CTA tile 128x128, BK=32, 256 threads (8 warps: 2m x 4n, warp tile 64x32).
// A,W bf16 streamed via 2-stage cp.async; fragments via ldmatrix / LDS.32; fp32 accum.
// grid = (NBLK * (DUAL?2:1), M/128); blockIdx.x fastest over N -> A reused in L2.
template <int KD, int NBLK, bool RES, bool DUAL>
__global__ void __launch_bounds__(256, 2) gemm_bf16(
    const __nv_bfloat16* __restrict__ A,
    const __nv_bfloat16* __restrict__ W0, const float* __restrict__ bias0, float* __restrict__ out0,
    const __nv_bfloat16* __restrict__ W1, const float* __restrict__ bias1, float* __restrict__ out1,
    const float* __restrict__ resid)
{
    constexpr int LDO = NBLK * 128;
    constexpr int STG = 128 * ROWB;           // 10240 bytes per operand tile
    __shared__ __align__(16) char smem[2 * 2 * STG];   // [stage][A|B]

    const int tid = threadIdx.x;
    const bool second = DUAL && (blockIdx.x >= NBLK);
    const int n0 = (DUAL ? (blockIdx.x % NBLK) : blockIdx.x) * 128;
    const int m0 = blockIdx.y * 128;
    const __nv_bfloat16* W = second ? W1 : W0;
    const float* bias = second ? bias1 : bias0;
    float* out = second ? out1 : out0;

    // cp.async producer mapping: 4 chunks of 16B per 64B row
    const int lc = tid & 3;
    const int lr = tid >> 2;                  // 0..63
    const __nv_bfloat16* Ag = A + (size_t)(m0 + lr) * KD + lc * 8;
    const __nv_bfloat16* Wg = W + (size_t)(n0 + lr) * KD + lc * 8;
    const unsigned smBase = (unsigned)__cvta_generic_to_shared(smem);
    const unsigned dBase = smBase + lr * ROWB + lc * 16;

    const int lane = tid & 31, warp = tid >> 5;
    const int wm = (warp & 1) * 64;
    const int wn = (warp >> 1) * 32;

    // ldmatrix per-lane offset: row = wm + (lane&15) (+mt*16), 16B col = lane>>4 (+ks*2)
    const unsigned aOff = (unsigned)((wm + (lane & 15)) * ROWB + (lane >> 4) * 16);
    // B fragment: row n = wn + lane>>2 (+nt*8), byte = (lane&3)*4 (+ks*32), b1 at +16
    const unsigned bOff = (unsigned)((wn + (lane >> 2)) * ROWB + (lane & 3) * 4);

    float acc[4][4][4];
#pragma unroll
    for (int a = 0; a < 4; ++a)
#pragma unroll
        for (int b = 0; b < 4; ++b)
#pragma unroll
            for (int c = 0; c < 4; ++c) acc[a][b][c] = 0.f;

    constexpr int NK = KD / 32;

    // prologue: stage 0
    {
        unsigned d = dBase;
        CPA(d, Ag);              CPA(d + 64 * ROWB, Ag + (size_t)64 * KD);
        CPA(d + STG, Wg);        CPA(d + STG + 64 * ROWB, Wg + (size_t)64 * KD);
        CP_COMMIT();
    }

    for (int kt = 0; kt < NK; ++kt) {
        const int s = kt & 1;
        if (kt + 1 < NK) {
            const __nv_bfloat16* a1 = Ag + (size_t)(kt + 1) * 32;
            const __nv_bfloat16* w1p = Wg + (size_t)(kt + 1) * 32;
            unsigned d = dBase + (s ^ 1) * 2 * STG;
            CPA(d, a1);           CPA(d + 64 * ROWB, a1 + (size_t)64 * KD);
            CPA(d + STG, w1p);    CPA(d + STG + 64 * ROWB, w1p + (size_t)64 * KD);
            CP_COMMIT();
            CP_WAIT(1);
        } else {
            CP_WAIT(0);
        }
        __syncthreads();

        const unsigned aBase = smBase + s * 2 * STG;
        const char* bGen = smem + s * 2 * STG + STG;

#pragma unroll
        for (int ks = 0; ks < 2; ++ks) {
            unsigned afr[4][4];
#pragma unroll
            for (int mt = 0; mt < 4; ++mt)
                ldm_x4(afr[mt][0], afr[mt][1], afr[mt][2], afr[mt][3],
                       aBase + aOff + mt * 16 * ROWB + ks * 32);
            unsigned bfr[4][2];
#pragma unroll
            for (int nt = 0; nt < 4; ++nt) {
                const char* p = bGen + bOff + nt * 8 * ROWB + ks * 32;
                bfr[nt][0] = *(const unsigned*)(p);
                bfr[nt][1] = *(const unsigned*)(p + 16);
            }
#pragma unroll
            for (int mt = 0; mt < 4; ++mt)
#pragma unroll
                for (int nt = 0; nt < 4; ++nt)
                    mma_bf16(acc[mt][nt], afr[mt], bfr[nt]);
        }
        __syncthreads();
    }

    // epilogue
    const int cRow = lane >> 2;
    const int cCol = (lane & 3) * 2;
#pragma unroll
    for (int mt = 0; mt < 4; ++mt) {
#pragma unroll
        for (int nt = 0; nt < 4; ++nt) {
            const int col = n0 + wn + nt * 8 + cCol;
            const float b0v = bias[col];
            const float b1v = bias[col + 1];
#pragma unroll
            for (int half = 0; half < 2; ++half) {
                const int row = m0 + wm + mt * 16 + cRow + half * 8;
                float2 v;
                v.x = acc[mt][nt][half * 2 + 0] + b0v;
                v.y = acc[mt][nt][half * 2 + 1] + b1v;
                if (RES) {
                    const float2 r = *(const float2*)(resid + (size_t)row * LDO + col);
                    v.x += r.x; v.y += r.y;
                }
                *(float2*)(out + (size_t)row * LDO + col) = v;
            }
        }
    }
}

// ---------------- fused attention core: per (l, h) ----------------
__global__ void __launch_bounds__(256) attn_kernel() {
    const int l = blockIdx.x;
    const int h = blockIdx.y;
    const int tid = threadIdx.x;

    __shared__ float bufA[64][68];
    __shared__ float bufB[64][68];

    const size_t base = (size_t)l * 64 * AH + (size_t)h * HD;
    const int sg = tid >> 4;
    const int dg = tid & 15;

#pragma unroll
    for (int it = 0; it < 4; ++it) {
        const int s = sg + it * 16;
        float4 qv = *(const float4*)(g_q + base + (size_t)s * AH + dg * 4);
        *(float4*)&bufA[s][dg * 4] = qv;
        float4 kv = *(const float4*)(g_k + base + (size_t)s * AH + dg * 4);
        bufB[dg * 4 + 0][s] = kv.x;
        bufB[dg * 4 + 1][s] = kv.y;
        bufB[dg * 4 + 2][s] = kv.z;
        bufB[dg * 4 + 3][s] = kv.w;
    }
    __syncthreads();

    const int r0 = sg * 4;
    const int c0 = dg * 4;

    float acc[4][4] = {};
#pragma unroll 8
    for (int kk = 0; kk < 64; ++kk) {
        float4 kv = *(const float4*)&bufB[kk][c0];
        float q0 = bufA[r0 + 0][kk];
        float q1 = bufA[r0 + 1][kk];
        float q2 = bufA[r0 + 2][kk];
        float q3 = bufA[r0 + 3][kk];
        acc[0][0] += q0 * kv.x; acc[0][1] += q0 * kv.y; acc[0][2] += q0 * kv.z; acc[0][3] += q0 * kv.w;
        acc[1][0] += q1 * kv.x; acc[1][1] += q1 * kv.y; acc[1][2] += q1 * kv.z; acc[1][3] += q1 * kv.w;
        acc[2][0] += q2 * kv.x; acc[2][1] += q2 * kv.y; acc[2][2] += q2 * kv.z; acc[2][3] += q2 * kv.w;
        acc[3][0] += q3 * kv.x; acc[3][1] += q3 * kv.y; acc[3][2] += q3 * kv.z; acc[3][3] += q3 * kv.w;
    }
#pragma unroll
    for (int i = 0; i < 4; ++i)
#pragma unroll
        for (int j = 0; j < 4; ++j)
            acc[i][j] = acc[i][j] * 0.125f + g_bias[(r0 + i) * 64 + c0 + j];
    __syncthreads();

#pragma unroll
    for (int i = 0; i < 4; ++i) {
        float m = fmaxf(fmaxf(acc[i][0], acc[i][1]), fmaxf(acc[i][2], acc[i][3]));
#pragma unroll
        for (int o = 8; o; o >>= 1) m = fmaxf(m, __shfl_xor_sync(0xffffffffu, m, o));
        float s = 0.f;
#pragma unroll
        for (int j = 0; j < 4; ++j) { acc[i][j] = __expf(acc[i][j] - m); s += acc[i][j]; }
#pragma unroll
        for (int o = 8; o; o >>= 1) s += __shfl_xor_sync(0xffffffffu, s, o);
        const float inv = 1.f / s;
#pragma unroll
        for (int j = 0; j < 4; ++j) acc[i][j] *= inv;
        float4 p4; p4.x = acc[i][0]; p4.y = acc[i][1]; p4.z = acc[i][2]; p4.w = acc[i][3];
        *(float4*)&bufA[r0 + i][c0] = p4;
    }

#pragma unroll
    for (int it = 0; it < 4; ++it) {
        const int s = sg + it * 16;
        float4 vv = *(const float4*)(g_v + base + (size_t)s * AH + dg * 4);
        *(float4*)&bufB[s][dg * 4] = vv;
    }
    __syncthreads();

    float o[4][4] = {};
#pragma unroll 8
    for (int cc = 0; cc < 64; ++cc) {
        float4 vv = *(const float4*)&bufB[cc][c0];
        float p0 = bufA[r0 + 0][cc];
        float p1 = bufA[r0 + 1][cc];
        float p2 = bufA[r0 + 2][cc];
        float p3 = bufA[r0 + 3][cc];
        o[0][0] += p0 * vv.x; o[0][1] += p0 * vv.y; o[0][2] += p0 * vv.z; o[0][3] += p0 * vv.w;
        o[1][0] += p1 * vv.x; o[1][1] += p1 * vv.y; o[1][2] += p1 * vv.z; o[1][3] += p1 * vv.w;
        o[2][0] += p2 * vv.x; o[2][1] += p2 * vv.y; o[2][2] += p2 * vv.z; o[2][3] += p2 * vv.w;
        o[3][0] += p3 * vv.x; o[3][1] += p3 * vv.y; o[3][2] += p3 * vv.z; o[3][3] += p3 * vv.w;
    }
#pragma unroll
    for (int i = 0; i < 4; ++i) {
        unsigned u0 = pack_bf(o[i][0], o[i][1]);
        unsigned u1 = pack_bf(o[i][2], o[i][3]);
        *(uint2*)(g_ctxb + base + (size_t)(r0 + i) * AH + c0) = make_uint2(u0, u1);
    }
}

// ---------------- LayerNorm (in place on d_out rows of 768) ----------------
__global__ void __launch_bounds__(256) ln_kernel(float* __restrict__ x,
                                                 const float* __restrict__ g,
                                                 const float* __restrict__ b) {
    const size_t row = blockIdx.x;
    float* p = x + row * H_DIM;
    const int tid = threadIdx.x;

    float v0 = p[tid], v1 = p[tid + 256], v2 = p[tid + 512];
    float s = v0 + v1 + v2;
    float q = v0 * v0 + v1 * v1 + v2 * v2;
#pragma unroll
    for (int o = 16; o; o >>= 1) {
        s += __shfl_xor_sync(0xffffffffu, s, o);
        q += __shfl_xor_sync(0xffffffffu, q, o);
    }
    __shared__ float ss[8], qs[8];
    __shared__ float mu_s, rs_s;
    if ((tid & 31) == 0) { ss[tid >> 5] = s; qs[tid >> 5] = q; }
    __syncthreads();
    if (tid == 0) {
        float S = 0.f, Q = 0.f;
#pragma unroll
        for (int i = 0; i < 8; ++i) { S += ss[i]; Q += qs[i]; }
        const float mu = S * (1.f / 768.f);
        const float var = Q * (1.f / 768.f) - mu * mu;
        mu_s = mu;
        rs_s = rsqrtf(var + 1e-12f);
    }
    __syncthreads();
    const float mu = mu_s, rs = rs_s;
    p[tid]       = (v0 - mu) * rs * g[tid]       + b[tid];
    p[tid + 256] = (v1 - mu) * rs * g[tid + 256] + b[tid + 256];
    p[tid + 512] = (v2 - mu) * rs * g[tid + 512] + b[tid + 512];
}

// ---------------- launch ----------------
extern "C" void kernel_launch(void* const* d_in, const int* in_sizes, int n_in,
                              void* d_out, int out_size) {
    const float* hidden = (const float*)d_in[0];
    const float* source = (const float*)d_in[1];
    const float* amask  = (const float*)d_in[2];
    const float* phylo  = (const float*)d_in[3];
    const float* cP     = (const float*)d_in[4];
    const float* w1     = (const float*)d_in[5];
    const float* w2     = (const float*)d_in[6];
    const float* Wq     = (const float*)d_in[7];
    const float* bq     = (const float*)d_in[8];
    const float* Wk     = (const float*)d_in[9];
    const float* bk     = (const float*)d_in[10];
    const float* Wv     = (const float*)d_in[11];
    const float* bv     = (const float*)d_in[12];
    const float* Wo     = (const float*)d_in[13];
    const float* bo     = (const float*)d_in[14];
    const float* lng    = (const float*)d_in[15];
    const float* lnb    = (const float*)d_in[16];
    float* out = (float*)d_out;

    void *hb, *sb, *cb, *qa, *ka, *va, *wqb, *wkb, *wvb, *wob;
    cudaGetSymbolAddress(&hb, g_hidb);
    cudaGetSymbolAddress(&sb, g_srcb);
    cudaGetSymbolAddress(&cb, g_ctxb);
    cudaGetSymbolAddress(&qa, g_q);
    cudaGetSymbolAddress(&ka, g_k);
    cudaGetSymbolAddress(&va, g_v);
    cudaGetSymbolAddress(&wqb, g_Wqb);
    cudaGetSymbolAddress(&wkb, g_Wkb);
    cudaGetSymbolAddress(&wvb, g_Wvb);
    cudaGetSymbolAddress(&wob, g_Wob);

    cvt_act<<<2048, 256>>>((const float4*)hidden, (const float4*)source);
    cvt_w<<<dim3(288, 4), 256>>>((const float4*)Wq, (const float4*)Wk,
                                 (const float4*)Wv, (const float4*)Wo);
    bias_kernel<<<1, 256>>>(phylo, amask, cP, w1, w2);

    // Q projection: grid.x over N blocks (L2 reuse of A)
    gemm_bf16<768, 3, false, false><<<dim3(3, 512), 256>>>(
        (const __nv_bfloat16*)hb, (const __nv_bfloat16*)wqb, bq, (float*)qa,
        nullptr, nullptr, nullptr, nullptr);
    // K + V fused (shared A = source)
    gemm_bf16<768, 3, false, true><<<dim3(6, 512), 256>>>(
        (const __nv_bfloat16*)sb, (const __nv_bfloat16*)wkb, bk, (float*)ka,
        (const __nv_bfloat16*)wvb, bv, (float*)va, nullptr);

    attn_kernel<<<dim3(L_DIM, NH), 256>>>();

    // Output projection + bias + residual
    gemm_bf16<384, 6, true, false><<<dim3(6, 512), 256>>>(
        (const __nv_bfloat16*)cb, (const __nv_bfloat16*)wob, bo, out,
        nullptr, nullptr, nullptr, hidden);

    ln_kernel<<<M_TOK, 256>>>(out, lng, lnb);
}

// round 4
// speedup vs baseline: 3.0586x; 1.8070x over previous
#include <cuda_runtime.h>
#include <cuda_bf16.h>
#include <math.h>
#include <stdint.h>

#define L_DIM   1024
#define S_DIM   64
#define H_DIM   768
#define AH      384
#define NH      6
#define HD      64
#define M_TOK   65536
#define MAX_DIST 20.0f
#define ROWB    80          // padded smem row bytes for GEMM tiles

// ---------------- scratch (device globals; no allocs allowed) ----------------
__device__ __align__(16) __nv_bfloat16 g_hidb[M_TOK * H_DIM];
__device__ __align__(16) __nv_bfloat16 g_srcb[M_TOK * H_DIM];
__device__ __align__(16) __nv_bfloat16 g_qb[M_TOK * AH];
__device__ __align__(16) __nv_bfloat16 g_kb[M_TOK * AH];
__device__ __align__(16) __nv_bfloat16 g_vb[M_TOK * AH];
__device__ __align__(16) __nv_bfloat16 g_ctxb[M_TOK * AH];
__device__ __align__(16) __nv_bfloat16 g_Wqb[AH * H_DIM];
__device__ __align__(16) __nv_bfloat16 g_Wkb[AH * H_DIM];
__device__ __align__(16) __nv_bfloat16 g_Wvb[AH * H_DIM];
__device__ __align__(16) __nv_bfloat16 g_Wob[H_DIM * AH];
__device__ __align__(16) float g_bias[S_DIM * S_DIM];

// ---------------- asm helpers ----------------
#define CPA(dst, src) asm volatile("cp.async.cg.shared.global [%0], [%1], 16;" :: "r"(dst), "l"(src))
#define CP_COMMIT()   asm volatile("cp.async.commit_group;")
#define CP_WAIT(n)    asm volatile("cp.async.wait_group %0;" :: "n"(n))

__device__ __forceinline__ void ldm_x4(unsigned& r0, unsigned& r1, unsigned& r2, unsigned& r3,
                                       unsigned addr) {
    asm volatile("ldmatrix.sync.aligned.m8n8.x4.shared.b16 {%0,%1,%2,%3}, [%4];"
                 : "=r"(r0), "=r"(r1), "=r"(r2), "=r"(r3) : "r"(addr));
}
__device__ __forceinline__ void ldm_x4t(unsigned& r0, unsigned& r1, unsigned& r2, unsigned& r3,
                                        unsigned addr) {
    asm volatile("ldmatrix.sync.aligned.m8n8.x4.trans.shared.b16 {%0,%1,%2,%3}, [%4];"
                 : "=r"(r0), "=r"(r1), "=r"(r2), "=r"(r3) : "r"(addr));
}

__device__ __forceinline__ void mma_bf16(float* c, const unsigned* a, const unsigned* b) {
    asm volatile(
        "mma.sync.aligned.m16n8k16.row.col.f32.bf16.bf16.f32 "
        "{%0,%1,%2,%3},{%4,%5,%6,%7},{%8,%9},{%0,%1,%2,%3};"
        : "+f"(c[0]), "+f"(c[1]), "+f"(c[2]), "+f"(c[3])
        : "r"(a[0]), "r"(a[1]), "r"(a[2]), "r"(a[3]), "r"(b[0]), "r"(b[1]));
}

__device__ __forceinline__ unsigned pack_bf(float a, float b) {
    __nv_bfloat162 t = __floats2bfloat162_rn(a, b);   // a -> low, b -> high
    return *reinterpret_cast<unsigned*>(&t);
}

// ---------------- fp32 -> bf16 conversion passes ----------------
__global__ void __launch_bounds__(256) cvt_act(const float4* __restrict__ hid,
                                               const float4* __restrict__ src) {
    const int n = M_TOK * H_DIM / 4;
    uint2* oh = reinterpret_cast<uint2*>(g_hidb);
    uint2* os = reinterpret_cast<uint2*>(g_srcb);
    for (int i = blockIdx.x * blockDim.x + threadIdx.x; i < n; i += gridDim.x * blockDim.x) {
        float4 h = hid[i];
        oh[i] = make_uint2(pack_bf(h.x, h.y), pack_bf(h.z, h.w));
        float4 s = src[i];
        os[i] = make_uint2(pack_bf(s.x, s.y), pack_bf(s.z, s.w));
    }
}

__global__ void __launch_bounds__(256) cvt_w(const float4* __restrict__ wq,
                                             const float4* __restrict__ wk,
                                             const float4* __restrict__ wv,
                                             const float4* __restrict__ wo) {
    const int per = AH * H_DIM / 4;
    const int a = blockIdx.y;
    const float4* src = (a == 0) ? wq : (a == 1) ? wk : (a == 2) ? wv : wo;
    uint2* dst = (a == 0) ? (uint2*)g_Wqb : (a == 1) ? (uint2*)g_Wkb
               : (a == 2) ? (uint2*)g_Wvb : (uint2*)g_Wob;
    for (int i = blockIdx.x * blockDim.x + threadIdx.x; i < per; i += gridDim.x * blockDim.x) {
        float4 v = src[i];
        dst[i] = make_uint2(pack_bf(v.x, v.y), pack_bf(v.z, v.w));
    }
}

// ---------------- FIRE bias + attention mask ----------------
__global__ void bias_kernel(const float* __restrict__ phylo, const float* __restrict__ am,
                            const float* __restrict__ cPtr, const float* __restrict__ w1,
                            const float* __restrict__ w2) {
    float c = fmaxf(cPtr[0], 0.f);
    float denom = logf(c * MAX_DIST + 1.f);
    for (int idx = threadIdx.x; idx < S_DIM * S_DIM; idx += blockDim.x) {
        int k = idx & 63;
        float r = logf(c * phylo[idx] + 1.f) / denom;
        float b = 0.f;
#pragma unroll
        for (int f = 0; f < 32; ++f) {
            float t = r * w1[f];
            float h = t / (1.f + __expf(-t));
            b += h * w2[f];
        }
        g_bias[idx] = b + am[k];
    }
}

// ---------------- bf16 tensor-core GEMM (4-stage cp.async ring) ----------------
// C[M,N] = A[M,K] @ W[N,K]^T (+bias)(+resid). CTA tile 128x128, BK=32.
// 256 threads (8 warps: 2m x 4n, warp tile 64x32). fp32 accum.
// OBF: write bf16 output (for q/k/v/ctx); else fp32.
template <int KD, int NBLK, bool RES, bool DUAL, bool OBF>
__global__ void __launch_bounds__(256, 2) gemm_bf16(
    const __nv_bfloat16* __restrict__ A,
    const __nv_bfloat16* __restrict__ W0, const float* __restrict__ bias0, void* __restrict__ out0,
    const __nv_bfloat16* __restrict__ W1, const float* __restrict__ bias1, void* __restrict__ out1,
    const float* __restrict__ resid)
{
    constexpr int LDO = NBLK * 128;
    constexpr int STG = 128 * ROWB;           // 10240 bytes per operand tile
    constexpr int NSTG = 4;
    extern __shared__ __align__(16) char smem[];   // NSTG * 2 * STG

    const int tid = threadIdx.x;
    const bool second = DUAL && (blockIdx.x >= NBLK);
    const int n0 = (DUAL ? (blockIdx.x % NBLK) : blockIdx.x) * 128;
    const int m0 = blockIdx.y * 128;
    const __nv_bfloat16* W = second ? W1 : W0;
    const float* bias = second ? bias1 : bias0;
    void* out = second ? out1 : out0;

    const int lc = tid & 3;
    const int lr = tid >> 2;                  // 0..63
    const __nv_bfloat16* Ag = A + (size_t)(m0 + lr) * KD + lc * 8;
    const __nv_bfloat16* Wg = W + (size_t)(n0 + lr) * KD + lc * 8;
    const unsigned smBase = (unsigned)__cvta_generic_to_shared(smem);
    const unsigned dBase = smBase + lr * ROWB + lc * 16;

    const int lane = tid & 31, warp = tid >> 5;
    const int wm = (warp & 1) * 64;
    const int wn = (warp >> 1) * 32;

    const unsigned aOff = (unsigned)((wm + (lane & 15)) * ROWB + (lane >> 4) * 16);
    const unsigned bOff = (unsigned)((wn + (lane >> 2)) * ROWB + (lane & 3) * 4);

    float acc[4][4][4];
#pragma unroll
    for (int a = 0; a < 4; ++a)
#pragma unroll
        for (int b = 0; b < 4; ++b)
#pragma unroll
            for (int c = 0; c < 4; ++c) acc[a][b][c] = 0.f;

    constexpr int NK = KD / 32;

    // prologue: fill stages 0..NSTG-2
#pragma unroll
    for (int i = 0; i < NSTG - 1; ++i) {
        const __nv_bfloat16* a = Ag + (size_t)i * 32;
        const __nv_bfloat16* wp = Wg + (size_t)i * 32;
        unsigned d = dBase + i * 2 * STG;
        CPA(d, a);           CPA(d + 64 * ROWB, a + (size_t)64 * KD);
        CPA(d + STG, wp);    CPA(d + STG + 64 * ROWB, wp + (size_t)64 * KD);
        CP_COMMIT();
    }

    for (int kt = 0; kt < NK; ++kt) {
        CP_WAIT(NSTG - 2);
        __syncthreads();

        const int nf = kt + NSTG - 1;
        if (nf < NK) {
            const __nv_bfloat16* a = Ag + (size_t)nf * 32;
            const __nv_bfloat16* wp = Wg + (size_t)nf * 32;
            unsigned d = dBase + (nf & 3) * 2 * STG;
            CPA(d, a);           CPA(d + 64 * ROWB, a + (size_t)64 * KD);
            CPA(d + STG, wp);    CPA(d + STG + 64 * ROWB, wp + (size_t)64 * KD);
        }
        CP_COMMIT();

        const unsigned aBase = smBase + (kt & 3) * 2 * STG;
        const char* bGen = smem + (kt & 3) * 2 * STG + STG;

#pragma unroll
        for (int ks = 0; ks < 2; ++ks) {
            unsigned afr[4][4];
#pragma unroll
            for (int mt = 0; mt < 4; ++mt)
                ldm_x4(afr[mt][0], afr[mt][1], afr[mt][2], afr[mt][3],
                       aBase + aOff + mt * 16 * ROWB + ks * 32);
            unsigned bfr[4][2];
#pragma unroll
            for (int nt = 0; nt < 4; ++nt) {
                const char* p = bGen + bOff + nt * 8 * ROWB + ks * 32;
                bfr[nt][0] = *(const unsigned*)(p);
                bfr[nt][1] = *(const unsigned*)(p + 16);
            }
#pragma unroll
            for (int mt = 0; mt < 4; ++mt)
#pragma unroll
                for (int nt = 0; nt < 4; ++nt)
                    mma_bf16(acc[mt][nt], afr[mt], bfr[nt]);
        }
    }

    // epilogue
    const int cRow = lane >> 2;
    const int cCol = (lane & 3) * 2;
#pragma unroll
    for (int mt = 0; mt < 4; ++mt) {
#pragma unroll
        for (int nt = 0; nt < 4; ++nt) {
            const int col = n0 + wn + nt * 8 + cCol;
            const float b0v = bias[col];
            const float b1v = bias[col + 1];
#pragma unroll
            for (int half = 0; half < 2; ++half) {
                const int row = m0 + wm + mt * 16 + cRow + half * 8;
                float vx = acc[mt][nt][half * 2 + 0] + b0v;
                float vy = acc[mt][nt][half * 2 + 1] + b1v;
                if (RES) {
                    const float2 r = *(const float2*)(resid + (size_t)row * LDO + col);
                    vx += r.x; vy += r.y;
                }
                if (OBF) {
                    *(unsigned*)((__nv_bfloat16*)out + (size_t)row * LDO + col) = pack_bf(vx, vy);
                } else {
                    float2 v; v.x = vx; v.y = vy;
                    *(float2*)((float*)out + (size_t)row * LDO + col) = v;
                }
            }
        }
    }
}

// ---------------- tensor-core attention: one CTA per (l, h), 128 threads ----------------
// S = q@k^T * 0.125 + bias ; softmax rows ; ctx = P@v. All bf16 mma, fp32 softmax.
__global__ void __launch_bounds__(128) attn_kernel() {
    __shared__ __align__(16) __nv_bfloat16 qs[64 * 72];
    __shared__ __align__(16) __nv_bfloat16 ks_[64 * 72];
    __shared__ __align__(16) __nv_bfloat16 vs[64 * 72];
    __shared__ __align__(16) float bs[64 * 68];

    const int l = blockIdx.x, h = blockIdx.y;
    const int tid = threadIdx.x;
    const int lane = tid & 31, w = tid >> 5;
    const size_t base = (size_t)l * 64 * AH + (size_t)h * HD;

    // load q, k, v tiles (rows of 64 bf16 = 128B; 8 threads per row)
    {
        const int r = tid >> 3, c8 = (tid & 7) * 8;
#pragma unroll
        for (int it = 0; it < 4; ++it) {
            const int s = it * 16 + r;
            const size_t g = base + (size_t)s * AH + c8;
            *(uint4*)&qs[s * 72 + c8] = *(const uint4*)(g_qb + g);
            *(uint4*)&ks_[s * 72 + c8] = *(const uint4*)(g_kb + g);
            *(uint4*)&vs[s * 72 + c8] = *(const uint4*)(g_vb + g);
        }
    }
    // bias tile 64x64 fp32
#pragma unroll
    for (int i = 0; i < 8; ++i) {
        const int idx = i * 128 + tid;           // 1024 float4
        const int r = idx >> 4, c = (idx & 15) * 4;
        *(float4*)&bs[r * 68 + c] = *(const float4*)(g_bias + r * 64 + c);
    }
    __syncthreads();

    const unsigned qB = (unsigned)__cvta_generic_to_shared(qs);
    const unsigned kB = (unsigned)__cvta_generic_to_shared(ks_);
    const unsigned vB = (unsigned)__cvta_generic_to_shared(vs);

    // ---- scores ----
    float sc[8][4];
#pragma unroll
    for (int i = 0; i < 8; ++i)
#pragma unroll
        for (int j = 0; j < 4; ++j) sc[i][j] = 0.f;

    const unsigned aAddr = qB + (unsigned)((w * 16 + (lane & 15)) * 144 + (lane >> 4) * 16);
    const unsigned bRow = (lane & 7) + ((lane >> 4) & 1) * 8;   // non-trans group row
    const unsigned bColB = ((lane >> 3) & 1) * 16;

#pragma unroll
    for (int ksx = 0; ksx < 4; ++ksx) {
        unsigned a[4];
        ldm_x4(a[0], a[1], a[2], a[3], aAddr + ksx * 32);
#pragma unroll
        for (int np = 0; np < 4; ++np) {
            unsigned b[4];
            ldm_x4(b[0], b[1], b[2], b[3],
                   kB + (unsigned)((np * 16 + bRow) * 144) + ksx * 32 + bColB);
            mma_bf16(sc[2 * np], a, b);
            mma_bf16(sc[2 * np + 1], a, b + 2);
        }
    }

    // ---- scale + bias + softmax ----
    const int rLo = w * 16 + (lane >> 2);
    const int cQ = 2 * (lane & 3);
    float mLo = -1e30f, mHi = -1e30f;
#pragma unroll
    for (int nt = 0; nt < 8; ++nt) {
        const int cb = nt * 8 + cQ;
        sc[nt][0] = sc[nt][0] * 0.125f + bs[rLo * 68 + cb];
        sc[nt][1] = sc[nt][1] * 0.125f + bs[rLo * 68 + cb + 1];
        sc[nt][2] = sc[nt][2] * 0.125f + bs[(rLo + 8) * 68 + cb];
        sc[nt][3] = sc[nt][3] * 0.125f + bs[(rLo + 8) * 68 + cb + 1];
        mLo = fmaxf(mLo, fmaxf(sc[nt][0], sc[nt][1]));
        mHi = fmaxf(mHi, fmaxf(sc[nt][2], sc[nt][3]));
    }
#pragma unroll
    for (int o = 1; o <= 2; o <<= 1) {
        mLo = fmaxf(mLo, __shfl_xor_sync(0xffffffffu, mLo, o));
        mHi = fmaxf(mHi, __shfl_xor_sync(0xffffffffu, mHi, o));
    }
    float sLo = 0.f, sHi = 0.f;
#pragma unroll
    for (int nt = 0; nt < 8; ++nt) {
        sc[nt][0] = __expf(sc[nt][0] - mLo); sLo += sc[nt][0];
        sc[nt][1] = __expf(sc[nt][1] - mLo); sLo += sc[nt][1];
        sc[nt][2] = __expf(sc[nt][2] - mHi); sHi += sc[nt][2];
        sc[nt][3] = __expf(sc[nt][3] - mHi); sHi += sc[nt][3];
    }
#pragma unroll
    for (int o = 1; o <= 2; o <<= 1) {
        sLo += __shfl_xor_sync(0xffffffffu, sLo, o);
        sHi += __shfl_xor_sync(0xffffffffu, sHi, o);
    }
    const float iLo = 1.f / sLo, iHi = 1.f / sHi;
#pragma unroll
    for (int nt = 0; nt < 8; ++nt) {
        sc[nt][0] *= iLo; sc[nt][1] *= iLo;
        sc[nt][2] *= iHi; sc[nt][3] *= iHi;
    }

    // ---- ctx = P @ v ----
    float o[8][4];
#pragma unroll
    for (int i = 0; i < 8; ++i)
#pragma unroll
        for (int j = 0; j < 4; ++j) o[i][j] = 0.f;

    const unsigned vRow = (lane & 7) + ((lane >> 3) & 1) * 8;   // trans group row (k)
    const unsigned vColB = ((lane >> 4) & 1) * 16;              // trans group col (d)

#pragma unroll
    for (int kk = 0; kk < 4; ++kk) {
        unsigned ap[4];
        ap[0] = pack_bf(sc[2 * kk][0], sc[2 * kk][1]);
        ap[1] = pack_bf(sc[2 * kk][2], sc[2 * kk][3]);
        ap[2] = pack_bf(sc[2 * kk + 1][0], sc[2 * kk + 1][1]);
        ap[3] = pack_bf(sc[2 * kk + 1][2], sc[2 * kk + 1][3]);
#pragma unroll
        for (int dp = 0; dp < 4; ++dp) {
            unsigned b[4];
            ldm_x4t(b[0], b[1], b[2], b[3],
                    vB + (unsigned)((kk * 16 + vRow) * 144) + dp * 32 + vColB);
            mma_bf16(o[2 * dp], ap, b);
            mma_bf16(o[2 * dp + 1], ap, b + 2);
        }
    }

    // ---- store ctx bf16 ----
#pragma unroll
    for (int nt = 0; nt < 8; ++nt) {
        const int col = nt * 8 + cQ;
        *(unsigned*)(g_ctxb + base + (size_t)rLo * AH + col) = pack_bf(o[nt][0], o[nt][1]);
        *(unsigned*)(g_ctxb + base + (size_t)(rLo + 8) * AH + col) = pack_bf(o[nt][2], o[nt][3]);
    }
}

// ---------------- LayerNorm (in place on d_out rows of 768) ----------------
__global__ void __launch_bounds__(256) ln_kernel(float* __restrict__ x,
                                                 const float* __restrict__ g,
                                                 const float* __restrict__ b) {
    const size_t row = blockIdx.x;
    float* p = x + row * H_DIM;
    const int tid = threadIdx.x;

    float v0 = p[tid], v1 = p[tid + 256], v2 = p[tid + 512];
    float s = v0 + v1 + v2;
    float q = v0 * v0 + v1 * v1 + v2 * v2;
#pragma unroll
    for (int o = 16; o; o >>= 1) {
        s += __shfl_xor_sync(0xffffffffu, s, o);
        q += __shfl_xor_sync(0xffffffffu, q, o);
    }
    __shared__ float ss[8], qs[8];
    __shared__ float mu_s, rs_s;
    if ((tid & 31) == 0) { ss[tid >> 5] = s; qs[tid >> 5] = q; }
    __syncthreads();
    if (tid == 0) {
        float S = 0.f, Q = 0.f;
#pragma unroll
        for (int i = 0; i < 8; ++i) { S += ss[i]; Q += qs[i]; }
        const float mu = S * (1.f / 768.f);
        const float var = Q * (1.f / 768.f) - mu * mu;
        mu_s = mu;
        rs_s = rsqrtf(var + 1e-12f);
    }
    __syncthreads();
    const float mu = mu_s, rs = rs_s;
    p[tid]       = (v0 - mu) * rs * g[tid]       + b[tid];
    p[tid + 256] = (v1 - mu) * rs * g[tid + 256] + b[tid + 256];
    p[tid + 512] = (v2 - mu) * rs * g[tid + 512] + b[tid + 512];
}

// ---------------- launch ----------------
extern "C" void kernel_launch(void* const* d_in, const int* in_sizes, int n_in,
                              void* d_out, int out_size) {
    const float* hidden = (const float*)d_in[0];
    const float* source = (const float*)d_in[1];
    const float* amask  = (const float*)d_in[2];
    const float* phylo  = (const float*)d_in[3];
    const float* cP     = (const float*)d_in[4];
    const float* w1     = (const float*)d_in[5];
    const float* w2     = (const float*)d_in[6];
    const float* Wq     = (const float*)d_in[7];
    const float* bq     = (const float*)d_in[8];
    const float* Wk     = (const float*)d_in[9];
    const float* bk     = (const float*)d_in[10];
    const float* Wv     = (const float*)d_in[11];
    const float* bv     = (const float*)d_in[12];
    const float* Wo     = (const float*)d_in[13];
    const float* bo     = (const float*)d_in[14];
    const float* lng    = (const float*)d_in[15];
    const float* lnb    = (const float*)d_in[16];
    float* out = (float*)d_out;

    void *hb, *sb, *cb, *qa, *ka, *va, *wqb, *wkb, *wvb, *wob;
    cudaGetSymbolAddress(&hb, g_hidb);
    cudaGetSymbolAddress(&sb, g_srcb);
    cudaGetSymbolAddress(&cb, g_ctxb);
    cudaGetSymbolAddress(&qa, g_qb);
    cudaGetSymbolAddress(&ka, g_kb);
    cudaGetSymbolAddress(&va, g_vb);
    cudaGetSymbolAddress(&wqb, g_Wqb);
    cudaGetSymbolAddress(&wkb, g_Wkb);
    cudaGetSymbolAddress(&wvb, g_Wvb);
    cudaGetSymbolAddress(&wob, g_Wob);

    const int SMEM_GEMM = 4 * 2 * 128 * ROWB;   // 81920
    cudaFuncSetAttribute(gemm_bf16<768, 3, false, false, true>,
                         cudaFuncAttributeMaxDynamicSharedMemorySize, SMEM_GEMM);
    cudaFuncSetAttribute(gemm_bf16<768, 3, false, true, true>,
                         cudaFuncAttributeMaxDynamicSharedMemorySize, SMEM_GEMM);
    cudaFuncSetAttribute(gemm_bf16<384, 6, true, false, false>,
                         cudaFuncAttributeMaxDynamicSharedMemorySize, SMEM_GEMM);

    cvt_act<<<2048, 256>>>((const float4*)hidden, (const float4*)source);
    cvt_w<<<dim3(288, 4), 256>>>((const float4*)Wq, (const float4*)Wk,
                                 (const float4*)Wv, (const float4*)Wo);
    bias_kernel<<<1, 256>>>(phylo, amask, cP, w1, w2);

    // Q projection -> bf16
    gemm_bf16<768, 3, false, false, true><<<dim3(3, 512), 256, SMEM_GEMM>>>(
        (const __nv_bfloat16*)hb, (const __nv_bfloat16*)wqb, bq, qa,
        nullptr, nullptr, nullptr, nullptr);
    // K + V fused -> bf16
    gemm_bf16<768, 3, false, true, true><<<dim3(6, 512), 256, SMEM_GEMM>>>(
        (const __nv_bfloat16*)sb, (const __nv_bfloat16*)wkb, bk, ka,
        (const __nv_bfloat16*)wvb, bv, va, nullptr);

    attn_kernel<<<dim3(L_DIM, NH), 128>>>();

    // Output projection + bias + residual -> fp32
    gemm_bf16<384, 6, true, false, false><<<dim3(6, 512), 256, SMEM_GEMM>>>(
        (const __nv_bfloat16*)cb, (const __nv_bfloat16*)wob, bo, out,
        nullptr, nullptr, nullptr, hidden);

    ln_kernel<<<M_TOK, 256>>>(out, lng, lnb);
}

// round 6
// speedup vs baseline: 3.3272x; 1.0878x over previous
#include <cuda_runtime.h>
#include <cuda_bf16.h>
#include <math.h>
#include <stdint.h>

#define L_DIM   1024
#define S_DIM   64
#define H_DIM   768
#define AH      384
#define NH      6
#define HD      64
#define M_TOK   65536
#define MAX_DIST 20.0f
#define ROWB    80          // padded smem row bytes (32 bf16 + 16B pad) -> conflict-free ldmatrix

// ---------------- scratch (device globals; no allocs allowed) ----------------
__device__ __align__(16) __nv_bfloat16 g_hidb[M_TOK * H_DIM];
__device__ __align__(16) __nv_bfloat16 g_srcb[M_TOK * H_DIM];
__device__ __align__(16) __nv_bfloat16 g_qb[M_TOK * AH];
__device__ __align__(16) __nv_bfloat16 g_kb[M_TOK * AH];
__device__ __align__(16) __nv_bfloat16 g_vb[M_TOK * AH];
__device__ __align__(16) __nv_bfloat16 g_ctxb[M_TOK * AH];
__device__ __align__(16) __nv_bfloat16 g_Wqb[AH * H_DIM];
__device__ __align__(16) __nv_bfloat16 g_Wkb[AH * H_DIM];
__device__ __align__(16) __nv_bfloat16 g_Wvb[AH * H_DIM];
__device__ __align__(16) __nv_bfloat16 g_Wob[H_DIM * AH];
__device__ __align__(16) float g_bias[S_DIM * S_DIM];

// ---------------- asm helpers ----------------
#define CPA(dst, src) asm volatile("cp.async.cg.shared.global [%0], [%1], 16;" :: "r"(dst), "l"(src))
#define CP_COMMIT()   asm volatile("cp.async.commit_group;")
#define CP_WAIT(n)    asm volatile("cp.async.wait_group %0;" :: "n"(n))

__device__ __forceinline__ void ldm_x4(unsigned& r0, unsigned& r1, unsigned& r2, unsigned& r3,
                                       unsigned addr) {
    asm volatile("ldmatrix.sync.aligned.m8n8.x4.shared.b16 {%0,%1,%2,%3}, [%4];"
                 : "=r"(r0), "=r"(r1), "=r"(r2), "=r"(r3) : "r"(addr));
}
__device__ __forceinline__ void ldm_x4t(unsigned& r0, unsigned& r1, unsigned& r2, unsigned& r3,
                                        unsigned addr) {
    asm volatile("ldmatrix.sync.aligned.m8n8.x4.trans.shared.b16 {%0,%1,%2,%3}, [%4];"
                 : "=r"(r0), "=r"(r1), "=r"(r2), "=r"(r3) : "r"(addr));
}

__device__ __forceinline__ void mma_bf16(float* c, const unsigned* a, const unsigned* b) {
    asm volatile(
        "mma.sync.aligned.m16n8k16.row.col.f32.bf16.bf16.f32 "
        "{%0,%1,%2,%3},{%4,%5,%6,%7},{%8,%9},{%0,%1,%2,%3};"
        : "+f"(c[0]), "+f"(c[1]), "+f"(c[2]), "+f"(c[3])
        : "r"(a[0]), "r"(a[1]), "r"(a[2]), "r"(a[3]), "r"(b[0]), "r"(b[1]));
}

__device__ __forceinline__ unsigned pack_bf(float a, float b) {
    __nv_bfloat162 t = __floats2bfloat162_rn(a, b);
    return *reinterpret_cast<unsigned*>(&t);
}

// ---------------- fp32 -> bf16 conversion passes ----------------
__global__ void __launch_bounds__(256) cvt_act(const float4* __restrict__ hid,
                                               const float4* __restrict__ src) {
    const int n = M_TOK * H_DIM / 4;
    uint2* oh = reinterpret_cast<uint2*>(g_hidb);
    uint2* os = reinterpret_cast<uint2*>(g_srcb);
    for (int i = blockIdx.x * blockDim.x + threadIdx.x; i < n; i += gridDim.x * blockDim.x) {
        float4 h = hid[i];
        oh[i] = make_uint2(pack_bf(h.x, h.y), pack_bf(h.z, h.w));
        float4 s = src[i];
        os[i] = make_uint2(pack_bf(s.x, s.y), pack_bf(s.z, s.w));
    }
}

__global__ void __launch_bounds__(256) cvt_w(const float4* __restrict__ wq,
                                             const float4* __restrict__ wk,
                                             const float4* __restrict__ wv,
                                             const float4* __restrict__ wo) {
    const int per = AH * H_DIM / 4;
    const int a = blockIdx.y;
    const float4* src = (a == 0) ? wq : (a == 1) ? wk : (a == 2) ? wv : wo;
    uint2* dst = (a == 0) ? (uint2*)g_Wqb : (a == 1) ? (uint2*)g_Wkb
               : (a == 2) ? (uint2*)g_Wvb : (uint2*)g_Wob;
    for (int i = blockIdx.x * blockDim.x + threadIdx.x; i < per; i += gridDim.x * blockDim.x) {
        float4 v = src[i];
        dst[i] = make_uint2(pack_bf(v.x, v.y), pack_bf(v.z, v.w));
    }
}

// ---------------- FIRE bias + attention mask ----------------
__global__ void bias_kernel(const float* __restrict__ phylo, const float* __restrict__ am,
                            const float* __restrict__ cPtr, const float* __restrict__ w1,
                            const float* __restrict__ w2) {
    float c = fmaxf(cPtr[0], 0.f);
    float denom = logf(c * MAX_DIST + 1.f);
    for (int idx = threadIdx.x; idx < S_DIM * S_DIM; idx += blockDim.x) {
        int k = idx & 63;
        float r = logf(c * phylo[idx] + 1.f) / denom;
        float b = 0.f;
#pragma unroll
        for (int f = 0; f < 32; ++f) {
            float t = r * w1[f];
            float h = t / (1.f + __expf(-t));
            b += h * w2[f];
        }
        g_bias[idx] = b + am[k];
    }
}

// ---------------- bf16 tensor-core GEMM core (4-stage cp.async ring) ----------------
// C[M,N] = A[M,K] @ W[N,K]^T (+bias)(+resid). CTA tile 128x128, BK=32.
// 256 threads (8 warps: 2m x 4n, warp tile 64x32). fp32 accum. All fragments via ldmatrix.
// NSEL: number of (A,W,out) selections along blockIdx.x (each NBLK wide).
template <int KD, int NBLK, int NSEL, bool RES, bool OBF>
__global__ void __launch_bounds__(256, 2) gemm_bf16(
    const __nv_bfloat16* __restrict__ A0, const __nv_bfloat16* __restrict__ A12,
    const __nv_bfloat16* __restrict__ W0, const float* __restrict__ bias0, void* __restrict__ out0,
    const __nv_bfloat16* __restrict__ W1, const float* __restrict__ bias1, void* __restrict__ out1,
    const __nv_bfloat16* __restrict__ W2, const float* __restrict__ bias2, void* __restrict__ out2,
    const float* __restrict__ resid)
{
    constexpr int LDO = NBLK * 128;
    constexpr int STG = 128 * ROWB;           // 10240 bytes per operand tile
    constexpr int NSTG = 4;
    extern __shared__ __align__(16) char smem[];   // NSTG * 2 * STG

    const int tid = threadIdx.x;
    const int sel = (NSEL > 1) ? (blockIdx.x / NBLK) : 0;
    const int n0 = (NSEL > 1 ? (blockIdx.x % NBLK) : blockIdx.x) * 128;
    const int m0 = blockIdx.y * 128;
    const __nv_bfloat16* A = (sel == 0) ? A0 : A12;
    const __nv_bfloat16* W = (sel == 0) ? W0 : (sel == 1) ? W1 : W2;
    const float* bias = (sel == 0) ? bias0 : (sel == 1) ? bias1 : bias2;
    void* out = (sel == 0) ? out0 : (sel == 1) ? out1 : out2;

    const int lc = tid & 3;
    const int lr = tid >> 2;                  // 0..63
    const __nv_bfloat16* Ag = A + (size_t)(m0 + lr) * KD + lc * 8;
    const __nv_bfloat16* Wg = W + (size_t)(n0 + lr) * KD + lc * 8;
    const unsigned smBase = (unsigned)__cvta_generic_to_shared(smem);
    const unsigned dBase = smBase + lr * ROWB + lc * 16;

    const int lane = tid & 31, warp = tid >> 5;
    const int wm = (warp & 1) * 64;
    const int wn = (warp >> 1) * 32;

    // A fragment ldmatrix: row = wm + (lane&15) (+mt*16), 16B col = lane>>4 (+ks*2)
    const unsigned aOff = (unsigned)((wm + (lane & 15)) * ROWB + (lane >> 4) * 16);
    // B fragment ldmatrix (two 8-n tiles x two 8-k chunks per x4):
    // row = wn + np*16 + (lane&7) + ((lane>>4)&1)*8 ; byte col = ((lane>>3)&1)*16 + ks*32
    const unsigned bOff = (unsigned)((wn + (lane & 7) + ((lane >> 4) & 1) * 8) * ROWB
                                     + ((lane >> 3) & 1) * 16);

    float acc[4][4][4];
#pragma unroll
    for (int a = 0; a < 4; ++a)
#pragma unroll
        for (int b = 0; b < 4; ++b)
#pragma unroll
            for (int c = 0; c < 4; ++c) acc[a][b][c] = 0.f;

    constexpr int NK = KD / 32;

    // prologue: fill stages 0..NSTG-2
#pragma unroll
    for (int i = 0; i < NSTG - 1; ++i) {
        const __nv_bfloat16* a = Ag + (size_t)i * 32;
        const __nv_bfloat16* wp = Wg + (size_t)i * 32;
        unsigned d = dBase + i * 2 * STG;
        CPA(d, a);           CPA(d + 64 * ROWB, a + (size_t)64 * KD);
        CPA(d + STG, wp);    CPA(d + STG + 64 * ROWB, wp + (size_t)64 * KD);
        CP_COMMIT();
    }

    for (int kt = 0; kt < NK; ++kt) {
        CP_WAIT(NSTG - 2);
        __syncthreads();

        const int nf = kt + NSTG - 1;
        if (nf < NK) {
            const __nv_bfloat16* a = Ag + (size_t)nf * 32;
            const __nv_bfloat16* wp = Wg + (size_t)nf * 32;
            unsigned d = dBase + (nf & 3) * 2 * STG;
            CPA(d, a);           CPA(d + 64 * ROWB, a + (size_t)64 * KD);
            CPA(d + STG, wp);    CPA(d + STG + 64 * ROWB, wp + (size_t)64 * KD);
        }
        CP_COMMIT();

        const unsigned aBase = smBase + (kt & 3) * 2 * STG;
        const unsigned bBase = aBase + STG;

#pragma unroll
        for (int ks = 0; ks < 2; ++ks) {
            unsigned afr[4][4];
#pragma unroll
            for (int mt = 0; mt < 4; ++mt)
                ldm_x4(afr[mt][0], afr[mt][1], afr[mt][2], afr[mt][3],
                       aBase + aOff + mt * 16 * ROWB + ks * 32);
            unsigned bfr[4][2];
#pragma unroll
            for (int np = 0; np < 2; ++np) {
                unsigned b0, b1, b2, b3;
                ldm_x4(b0, b1, b2, b3, bBase + bOff + np * 16 * ROWB + ks * 32);
                bfr[2 * np][0] = b0;     bfr[2 * np][1] = b1;
                bfr[2 * np + 1][0] = b2; bfr[2 * np + 1][1] = b3;
            }
#pragma unroll
            for (int mt = 0; mt < 4; ++mt)
#pragma unroll
                for (int nt = 0; nt < 4; ++nt)
                    mma_bf16(acc[mt][nt], afr[mt], bfr[nt]);
        }
    }

    // epilogue
    const int cRow = lane >> 2;
    const int cCol = (lane & 3) * 2;
#pragma unroll
    for (int mt = 0; mt < 4; ++mt) {
#pragma unroll
        for (int nt = 0; nt < 4; ++nt) {
            const int col = n0 + wn + nt * 8 + cCol;
            const float b0v = bias[col];
            const float b1v = bias[col + 1];
#pragma unroll
            for (int half = 0; half < 2; ++half) {
                const int row = m0 + wm + mt * 16 + cRow + half * 8;
                float vx = acc[mt][nt][half * 2 + 0] + b0v;
                float vy = acc[mt][nt][half * 2 + 1] + b1v;
                if (RES) {
                    const float2 r = *(const float2*)(resid + (size_t)row * LDO + col);
                    vx += r.x; vy += r.y;
                }
                if (OBF) {
                    *(unsigned*)((__nv_bfloat16*)out + (size_t)row * LDO + col) = pack_bf(vx, vy);
                } else {
                    float2 v; v.x = vx; v.y = vy;
                    *(float2*)((float*)out + (size_t)row * LDO + col) = v;
                }
            }
        }
    }
}

// ---------------- tensor-core attention: one CTA per (l, h), 128 threads ----------------
__global__ void __launch_bounds__(128) attn_kernel() {
    __shared__ __align__(16) __nv_bfloat16 qs[64 * 72];
    __shared__ __align__(16) __nv_bfloat16 ks_[64 * 72];
    __shared__ __align__(16) __nv_bfloat16 vs[64 * 72];
    __shared__ __align__(16) float bs[64 * 68];

    const int l = blockIdx.x, h = blockIdx.y;
    const int tid = threadIdx.x;
    const int lane = tid & 31, w = tid >> 5;
    const size_t base = (size_t)l * 64 * AH + (size_t)h * HD;

    {
        const int r = tid >> 3, c8 = (tid & 7) * 8;
#pragma unroll
        for (int it = 0; it < 4; ++it) {
            const int s = it * 16 + r;
            const size_t g = base + (size_t)s * AH + c8;
            *(uint4*)&qs[s * 72 + c8] = *(const uint4*)(g_qb + g);
            *(uint4*)&ks_[s * 72 + c8] = *(const uint4*)(g_kb + g);
            *(uint4*)&vs[s * 72 + c8] = *(const uint4*)(g_vb + g);
        }
    }
#pragma unroll
    for (int i = 0; i < 8; ++i) {
        const int idx = i * 128 + tid;
        const int r = idx >> 4, c = (idx & 15) * 4;
        *(float4*)&bs[r * 68 + c] = *(const float4*)(g_bias + r * 64 + c);
    }
    __syncthreads();

    const unsigned qB = (unsigned)__cvta_generic_to_shared(qs);
    const unsigned kB = (unsigned)__cvta_generic_to_shared(ks_);
    const unsigned vB = (unsigned)__cvta_generic_to_shared(vs);

    float sc[8][4];
#pragma unroll
    for (int i = 0; i < 8; ++i)
#pragma unroll
        for (int j = 0; j < 4; ++j) sc[i][j] = 0.f;

    const unsigned aAddr = qB + (unsigned)((w * 16 + (lane & 15)) * 144 + (lane >> 4) * 16);
    const unsigned bRow = (lane & 7) + ((lane >> 4) & 1) * 8;
    const unsigned bColB = ((lane >> 3) & 1) * 16;

#pragma unroll
    for (int ksx = 0; ksx < 4; ++ksx) {
        unsigned a[4];
        ldm_x4(a[0], a[1], a[2], a[3], aAddr + ksx * 32);
#pragma unroll
        for (int np = 0; np < 4; ++np) {
            unsigned b[4];
            ldm_x4(b[0], b[1], b[2], b[3],
                   kB + (unsigned)((np * 16 + bRow) * 144) + ksx * 32 + bColB);
            mma_bf16(sc[2 * np], a, b);
            mma_bf16(sc[2 * np + 1], a, b + 2);
        }
    }

    const int rLo = w * 16 + (lane >> 2);
    const int cQ = 2 * (lane & 3);
    float mLo = -1e30f, mHi = -1e30f;
#pragma unroll
    for (int nt = 0; nt < 8; ++nt) {
        const int cb = nt * 8 + cQ;
        sc[nt][0] = sc[nt][0] * 0.125f + bs[rLo * 68 + cb];
        sc[nt][1] = sc[nt][1] * 0.125f + bs[rLo * 68 + cb + 1];
        sc[nt][2] = sc[nt][2] * 0.125f + bs[(rLo + 8) * 68 + cb];
        sc[nt][3] = sc[nt][3] * 0.125f + bs[(rLo + 8) * 68 + cb + 1];
        mLo = fmaxf(mLo, fmaxf(sc[nt][0], sc[nt][1]));
        mHi = fmaxf(mHi, fmaxf(sc[nt][2], sc[nt][3]));
    }
#pragma unroll
    for (int o = 1; o <= 2; o <<= 1) {
        mLo = fmaxf(mLo, __shfl_xor_sync(0xffffffffu, mLo, o));
        mHi = fmaxf(mHi, __shfl_xor_sync(0xffffffffu, mHi, o));
    }
    float sLo = 0.f, sHi = 0.f;
#pragma unroll
    for (int nt = 0; nt < 8; ++nt) {
        sc[nt][0] = __expf(sc[nt][0] - mLo); sLo += sc[nt][0];
        sc[nt][1] = __expf(sc[nt][1] - mLo); sLo += sc[nt][1];
        sc[nt][2] = __expf(sc[nt][2] - mHi); sHi += sc[nt][2];
        sc[nt][3] = __expf(sc[nt][3] - mHi); sHi += sc[nt][3];
    }
#pragma unroll
    for (int o = 1; o <= 2; o <<= 1) {
        sLo += __shfl_xor_sync(0xffffffffu, sLo, o);
        sHi += __shfl_xor_sync(0xffffffffu, sHi, o);
    }
    const float iLo = 1.f / sLo, iHi = 1.f / sHi;
#pragma unroll
    for (int nt = 0; nt < 8; ++nt) {
        sc[nt][0] *= iLo; sc[nt][1] *= iLo;
        sc[nt][2] *= iHi; sc[nt][3] *= iHi;
    }

    float o[8][4];
#pragma unroll
    for (int i = 0; i < 8; ++i)
#pragma unroll
        for (int j = 0; j < 4; ++j) o[i][j] = 0.f;

    const unsigned vRow = (lane & 7) + ((lane >> 3) & 1) * 8;
    const unsigned vColB = ((lane >> 4) & 1) * 16;

#pragma unroll
    for (int kk = 0; kk < 4; ++kk) {
        unsigned ap[4];
        ap[0] = pack_bf(sc[2 * kk][0], sc[2 * kk][1]);
        ap[1] = pack_bf(sc[2 * kk][2], sc[2 * kk][3]);
        ap[2] = pack_bf(sc[2 * kk + 1][0], sc[2 * kk + 1][1]);
        ap[3] = pack_bf(sc[2 * kk + 1][2], sc[2 * kk + 1][3]);
#pragma unroll
        for (int dp = 0; dp < 4; ++dp) {
            unsigned b[4];
            ldm_x4t(b[0], b[1], b[2], b[3],
                    vB + (unsigned)((kk * 16 + vRow) * 144) + dp * 32 + vColB);
            mma_bf16(o[2 * dp], ap, b);
            mma_bf16(o[2 * dp + 1], ap, b + 2);
        }
    }

#pragma unroll
    for (int nt = 0; nt < 8; ++nt) {
        const int col = nt * 8 + cQ;
        *(unsigned*)(g_ctxb + base + (size_t)rLo * AH + col) = pack_bf(o[nt][0], o[nt][1]);
        *(unsigned*)(g_ctxb + base + (size_t)(rLo + 8) * AH + col) = pack_bf(o[nt][2], o[nt][3]);
    }
}

// ---------------- LayerNorm (in place on d_out rows of 768) ----------------
__global__ void __launch_bounds__(256) ln_kernel(float* __restrict__ x,
                                                 const float* __restrict__ g,
                                                 const float* __restrict__ b) {
    const size_t row = blockIdx.x;
    float* p = x + row * H_DIM;
    const int tid = threadIdx.x;

    float v0 = p[tid], v1 = p[tid + 256], v2 = p[tid + 512];
    float s = v0 + v1 + v2;
    float q = v0 * v0 + v1 * v1 + v2 * v2;
#pragma unroll
    for (int o = 16; o; o >>= 1) {
        s += __shfl_xor_sync(0xffffffffu, s, o);
        q += __shfl_xor_sync(0xffffffffu, q, o);
    }
    __shared__ float ss[8], qs[8];
    __shared__ float mu_s, rs_s;
    if ((tid & 31) == 0) { ss[tid >> 5] = s; qs[tid >> 5] = q; }
    __syncthreads();
    if (tid == 0) {
        float S = 0.f, Q = 0.f;
#pragma unroll
        for (int i = 0; i < 8; ++i) { S += ss[i]; Q += qs[i]; }
        const float mu = S * (1.f / 768.f);
        const float var = Q * (1.f / 768.f) - mu * mu;
        mu_s = mu;
        rs_s = rsqrtf(var + 1e-12f);
    }
    __syncthreads();
    const float mu = mu_s, rs = rs_s;
    p[tid]       = (v0 - mu) * rs * g[tid]       + b[tid];
    p[tid + 256] = (v1 - mu) * rs * g[tid + 256] + b[tid + 256];
    p[tid + 512] = (v2 - mu) * rs * g[tid + 512] + b[tid + 512];
}

// ---------------- launch ----------------
extern "C" void kernel_launch(void* const* d_in, const int* in_sizes, int n_in,
                              void* d_out, int out_size) {
    const float* hidden = (const float*)d_in[0];
    const float* source = (const float*)d_in[1];
    const float* amask  = (const float*)d_in[2];
    const float* phylo  = (const float*)d_in[3];
    const float* cP     = (const float*)d_in[4];
    const float* w1     = (const float*)d_in[5];
    const float* w2     = (const float*)d_in[6];
    const float* Wq     = (const float*)d_in[7];
    const float* bq     = (const float*)d_in[8];
    const float* Wk     = (const float*)d_in[9];
    const float* bk     = (const float*)d_in[10];
    const float* Wv     = (const float*)d_in[11];
    const float* bv     = (const float*)d_in[12];
    const float* Wo     = (const float*)d_in[13];
    const float* bo     = (const float*)d_in[14];
    const float* lng    = (const float*)d_in[15];
    const float* lnb    = (const float*)d_in[16];
    float* out = (float*)d_out;

    void *hb, *sb, *cb, *qa, *ka, *va, *wqb, *wkb, *wvb, *wob;
    cudaGetSymbolAddress(&hb, g_hidb);
    cudaGetSymbolAddress(&sb, g_srcb);
    cudaGetSymbolAddress(&cb, g_ctxb);
    cudaGetSymbolAddress(&qa, g_qb);
    cudaGetSymbolAddress(&ka, g_kb);
    cudaGetSymbolAddress(&va, g_vb);
    cudaGetSymbolAddress(&wqb, g_Wqb);
    cudaGetSymbolAddress(&wkb, g_Wkb);
    cudaGetSymbolAddress(&wvb, g_Wvb);
    cudaGetSymbolAddress(&wob, g_Wob);

    const int SMEM_GEMM = 4 * 2 * 128 * ROWB;   // 81920
    cudaFuncSetAttribute(gemm_bf16<768, 3, 3, false, true>,
                         cudaFuncAttributeMaxDynamicSharedMemorySize, SMEM_GEMM);
    cudaFuncSetAttribute(gemm_bf16<384, 6, 1, true, false>,
                         cudaFuncAttributeMaxDynamicSharedMemorySize, SMEM_GEMM);

    cvt_act<<<2048, 256>>>((const float4*)hidden, (const float4*)source);
    cvt_w<<<dim3(288, 4), 256>>>((const float4*)Wq, (const float4*)Wk,
                                 (const float4*)Wv, (const float4*)Wo);
    bias_kernel<<<1, 256>>>(phylo, amask, cP, w1, w2);

    // fused Q + K + V projections -> bf16 (sel 0: hidden@Wq, sel 1: source@Wk, sel 2: source@Wv)
    gemm_bf16<768, 3, 3, false, true><<<dim3(9, 512), 256, SMEM_GEMM>>>(
        (const __nv_bfloat16*)hb, (const __nv_bfloat16*)sb,
        (const __nv_bfloat16*)wqb, bq, qa,
        (const __nv_bfloat16*)wkb, bk, ka,
        (const __nv_bfloat16*)wvb, bv, va,
        nullptr);

    attn_kernel<<<dim3(L_DIM, NH), 128>>>();

    // Output projection + bias + residual -> fp32
    gemm_bf16<384, 6, 1, true, false><<<dim3(6, 512), 256, SMEM_GEMM>>>(
        (const __nv_bfloat16*)cb, nullptr,
        (const __nv_bfloat16*)wob, bo, out,
        nullptr, nullptr, nullptr,
        nullptr, nullptr, nullptr,
        hidden);

    ln_kernel<<<M_TOK, 256>>>(out, lng, lnb);
}